// round 15
// baseline (speedup 1.0000x reference)
#include <cuda_runtime.h>
#include <cuda_bf16.h>
#include <stdint.h>
#include <math.h>

#define NBANKS 16
#define D 32
#define NIN 3072
#define NOUT 1000
#define BATCH 8192
#define BN_EPS 1e-5f
#define CB 128
#define PB 128

// ---------------- device scratch ----------------
__device__ float g_px1[PB * NIN];
__device__ float g_px2[PB * NIN];
__device__ float g_scale[NIN];
__device__ float g_shift[NIN];
__device__ float g_bpart[PB * 64];
__device__ __nv_bfloat16 g_xH[(size_t)BATCH * NIN];   // x split hi
__device__ __nv_bfloat16 g_xL[(size_t)BATCH * NIN];   // x split lo
__device__ __nv_bfloat16 g_WpH[NIN * 64];
__device__ __nv_bfloat16 g_WpL[NIN * 64];
__device__ float g_bp[64];
__device__ float g_in0[BATCH * D];
__device__ float g_in1[BATCH * D];
__device__ __nv_bfloat16 g_preTH[64 * BATCH];
__device__ __nv_bfloat16 g_preTL[64 * BATCH];
__device__ __nv_bfloat16 g_WoutH[64 * 1024];
__device__ __nv_bfloat16 g_WoutL[64 * 1024];
__device__ float g_p1s[NBANKS * CB * 32];
__device__ float g_p2s[NBANKS * CB * 32];
__device__ unsigned g_barc;
__device__ unsigned g_barg;
__device__ unsigned g_belect;
__device__ unsigned g_cflag[CB];
__device__ float g_tg_fallback[BATCH];

// ---------------- helpers ----------------
__device__ __forceinline__ unsigned smem_u32(const void* p) {
    return (unsigned)__cvta_generic_to_shared(p);
}
__device__ __forceinline__ void ldsm_x4(unsigned& r0, unsigned& r1, unsigned& r2,
                                        unsigned& r3, unsigned addr) {
    asm volatile("ldmatrix.sync.aligned.m8n8.x4.shared.b16 {%0,%1,%2,%3},[%4];"
                 : "=r"(r0), "=r"(r1), "=r"(r2), "=r"(r3) : "r"(addr));
}
__device__ __forceinline__ void ldsm_x4_t(unsigned& r0, unsigned& r1, unsigned& r2,
                                          unsigned& r3, unsigned addr) {
    asm volatile("ldmatrix.sync.aligned.m8n8.x4.trans.shared.b16 {%0,%1,%2,%3},[%4];"
                 : "=r"(r0), "=r"(r1), "=r"(r2), "=r"(r3) : "r"(addr));
}
__device__ __forceinline__ void mma_bf16(float* c, const unsigned* a,
                                         unsigned b0, unsigned b1) {
    asm volatile(
        "mma.sync.aligned.m16n8k16.row.col.f32.bf16.bf16.f32 "
        "{%0,%1,%2,%3},{%4,%5,%6,%7},{%8,%9},{%0,%1,%2,%3};"
        : "+f"(c[0]), "+f"(c[1]), "+f"(c[2]), "+f"(c[3])
        : "r"(a[0]), "r"(a[1]), "r"(a[2]), "r"(a[3]), "r"(b0), "r"(b1));
}
__device__ __forceinline__ unsigned pack_hi2(float x, float y) {
    __nv_bfloat16 hx = __float2bfloat16(x), hy = __float2bfloat16(y);
    return ((unsigned)__bfloat16_as_ushort(hy) << 16) | __bfloat16_as_ushort(hx);
}
__device__ __forceinline__ unsigned pack_lo2(float x, float y) {
    __nv_bfloat16 hx = __float2bfloat16(x), hy = __float2bfloat16(y);
    float lx = x - __bfloat162float(hx), ly = y - __bfloat162float(hy);
    __nv_bfloat16 bx = __float2bfloat16(lx), by = __float2bfloat16(ly);
    return ((unsigned)__bfloat16_as_ushort(by) << 16) | __bfloat16_as_ushort(bx);
}

__device__ __forceinline__ void grid_bar_n(int nblk) {
    __syncthreads();
    if (threadIdx.x == 0) {
        unsigned gen = *(volatile unsigned*)&g_barg;
        __threadfence();
        if (atomicAdd(&g_barc, 1u) == (unsigned)nblk - 1) {
            atomicExch(&g_barc, 0u);
            __threadfence();
            *(volatile unsigned*)&g_barg = gen + 1;
        } else {
            while (*(volatile unsigned*)&g_barg == gen) { }
        }
        __threadfence();
    }
    __syncthreads();
}

// ---------------- fused prep (stats + x bf16 split + weight fold) ----------
__global__ void __launch_bounds__(256, 1) prep_kernel(
    const float* __restrict__ x, const float* __restrict__ gamma,
    const float* __restrict__ beta, const float* __restrict__ W_in,
    const float* __restrict__ b_in) {
    int tid = threadIdx.x;
    int blk = blockIdx.x;
    int warp = tid >> 5, lane = tid & 31;

    if (blk == 0) {
        if (tid < CB) g_cflag[tid] = 0u;
        if (tid == 0) g_belect = 0u;
    }

    // phase 1: per-block x column stats + bf16 hi/lo split write
    {
        float s1[3][4], s2[3][4];
        #pragma unroll
        for (int g = 0; g < 3; g++)
            #pragma unroll
            for (int i = 0; i < 4; i++) { s1[g][i] = 0.f; s2[g][i] = 0.f; }
        int row0 = blk * 64;
        for (int r = 0; r < 64; r++) {
            size_t rowoff = (size_t)(row0 + r) * NIN;
            const float* xr = x + rowoff;
            #pragma unroll
            for (int g = 0; g < 3; g++) {
                float4 v = *(const float4*)&xr[g * 1024 + tid * 4];
                s1[g][0] += v.x; s2[g][0] += v.x * v.x;
                s1[g][1] += v.y; s2[g][1] += v.y * v.y;
                s1[g][2] += v.z; s2[g][2] += v.z * v.z;
                s1[g][3] += v.w; s2[g][3] += v.w * v.w;
                uint2 hv, lv;
                hv.x = pack_hi2(v.x, v.y); hv.y = pack_hi2(v.z, v.w);
                lv.x = pack_lo2(v.x, v.y); lv.y = pack_lo2(v.z, v.w);
                *(uint2*)&g_xH[rowoff + g * 1024 + tid * 4] = hv;
                *(uint2*)&g_xL[rowoff + g * 1024 + tid * 4] = lv;
            }
        }
        #pragma unroll
        for (int g = 0; g < 3; g++) {
            *(float4*)&g_px1[blk * NIN + g * 1024 + tid * 4] =
                make_float4(s1[g][0], s1[g][1], s1[g][2], s1[g][3]);
            *(float4*)&g_px2[blk * NIN + g * 1024 + tid * 4] =
                make_float4(s2[g][0], s2[g][1], s2[g][2], s2[g][3]);
        }
    }
    grid_bar_n(PB);
    // phase 2: finalize scale/shift for THIS block's 24 columns
    {
        #pragma unroll
        for (int cc = 0; cc < 3; cc++) {
            int col = blk * 24 + warp * 3 + cc;
            float a = 0.f, b = 0.f;
            #pragma unroll
            for (int q = 0; q < 4; q++) {
                a += g_px1[(lane + q * 32) * NIN + col];
                b += g_px2[(lane + q * 32) * NIN + col];
            }
            #pragma unroll
            for (int o = 16; o; o >>= 1) {
                a += __shfl_xor_sync(~0u, a, o);
                b += __shfl_xor_sync(~0u, b, o);
            }
            if (lane == 0) {
                float mean = a * (1.f / BATCH);
                float var = b * (1.f / BATCH) - mean * mean;
                float rstd = rsqrtf(var + BN_EPS);
                float sc = rstd * gamma[col];
                g_scale[col] = sc;
                g_shift[col] = beta[col] - mean * sc;
            }
        }
    }
    __syncthreads();
    // phase 3: fold weights (this block's 24 cols) + bias partials
    {
        __shared__ float sred[4][64];
        int j = tid & 63, grp = tid >> 6;
        int k = j >> 5, d = j & 31;
        float bias = 0.f;
        #pragma unroll
        for (int p = 0; p < 6; p++) {
            int c = blk * 24 + grp * 6 + p;
            float wraw = W_in[(size_t)k * NIN * D + c * D + d];
            float w = g_scale[c] * wraw;
            __nv_bfloat16 h = __float2bfloat16(w);
            g_WpH[c * 64 + j] = h;
            g_WpL[c * 64 + j] = __float2bfloat16(w - __bfloat162float(h));
            bias += g_shift[c] * wraw;
        }
        sred[grp][j] = bias;
        __syncthreads();
        if (tid < 64)
            g_bpart[blk * 64 + tid] =
                sred[0][tid] + sred[1][tid] + sred[2][tid] + sred[3][tid];
    }
    __syncthreads();
    __shared__ unsigned s_elect;
    if (tid == 0) {
        __threadfence();
        s_elect = (atomicAdd(&g_belect, 1u) == PB - 1) ? 1u : 0u;
    }
    __syncthreads();
    if (s_elect) {
        if (tid == 0) { atomicExch(&g_belect, 0u); __threadfence(); }
        __shared__ float sred2[4][64];
        int j = tid & 63, grp = tid >> 6;
        float s = 0.f;
        #pragma unroll 8
        for (int b = grp; b < PB; b += 4) s += __ldcg(&g_bpart[b * 64 + j]);
        sred2[grp][j] = s;
        __syncthreads();
        if (tid < 64)
            g_bp[tid] = b_in[tid] +
                sred2[0][tid] + sred2[1][tid] + sred2[2][tid] + sred2[3][tid];
    }
}

__global__ void woutfold_kernel(const float* __restrict__ Wout) {
    int n = blockIdx.x * 256 + threadIdx.x;
    #pragma unroll 8
    for (int k = 0; k < 64; k++) {
        int bank = k >> 5, d = k & 31;
        float w = (n < NOUT) ? Wout[(size_t)bank * D * NOUT + d * NOUT + n] : 0.f;
        __nv_bfloat16 h = __float2bfloat16(w);
        g_WoutH[k * 1024 + n] = h;
        g_WoutL[k * 1024 + n] = __float2bfloat16(w - __bfloat162float(h));
    }
}

// ---------------- input GEMM (pre-split A: staging is pure copies) ---------
#define APAD 40
#define BPAD 72
__global__ void __launch_bounds__(256) gemm_in_tc(const float* __restrict__ x) {
    __shared__ __nv_bfloat16 Ah[2][64 * APAD];
    __shared__ __nv_bfloat16 Al[2][64 * APAD];
    __shared__ __nv_bfloat16 Bh[2][32 * BPAD];
    __shared__ __nv_bfloat16 Bl[2][32 * BPAD];
    int tid = threadIdx.x;
    int w = tid >> 5, l = tid & 31;
    int wm = w & 3, wn = w >> 2;
    int rowBase = blockIdx.x * 64;

    int a_r0 = tid >> 2;            // row 0..63
    int a_k8 = (tid & 3) * 8;       // 8 bf16 per thread
    int b_kk = tid >> 3;
    int b_n8 = (tid & 7) * 8;

    uint4 pah, pal, pbh, pbl;
    pah = *(const uint4*)&g_xH[(size_t)(rowBase + a_r0) * NIN + a_k8];
    pal = *(const uint4*)&g_xL[(size_t)(rowBase + a_r0) * NIN + a_k8];
    pbh = *(const uint4*)&g_WpH[b_kk * 64 + b_n8];
    pbl = *(const uint4*)&g_WpL[b_kk * 64 + b_n8];
    {
        *(uint4*)&Ah[0][a_r0 * APAD + a_k8] = pah;
        *(uint4*)&Al[0][a_r0 * APAD + a_k8] = pal;
        *(uint4*)&Bh[0][b_kk * BPAD + b_n8] = pbh;
        *(uint4*)&Bl[0][b_kk * BPAD + b_n8] = pbl;
    }
    __syncthreads();

    float c[4][4];
    #pragma unroll
    for (int i = 0; i < 4; i++)
        #pragma unroll
        for (int j = 0; j < 4; j++) c[i][j] = 0.f;

    int a_row = wm * 16 + (l & 7) + ((l >> 3) & 1) * 8;
    int a_kof = (l >> 4) * 8;
    int b_k = (l & 7) + ((l >> 3) & 1) * 8;
    int b_n = (l >> 4) * 8;

    for (int kt = 0; kt < 96; kt++) {
        int cur = kt & 1, nxt = cur ^ 1;
        if (kt < 95) {
            int kb = (kt + 1) * 32;
            pah = *(const uint4*)&g_xH[(size_t)(rowBase + a_r0) * NIN + kb + a_k8];
            pal = *(const uint4*)&g_xL[(size_t)(rowBase + a_r0) * NIN + kb + a_k8];
            pbh = *(const uint4*)&g_WpH[(kb + b_kk) * 64 + b_n8];
            pbl = *(const uint4*)&g_WpL[(kb + b_kk) * 64 + b_n8];
        }
        unsigned ahb = smem_u32(Ah[cur]), alb = smem_u32(Al[cur]);
        unsigned bhb = smem_u32(Bh[cur]), blb = smem_u32(Bl[cur]);
        #pragma unroll
        for (int ks = 0; ks < 2; ks++) {
            int k0 = ks * 16;
            unsigned a_off = (unsigned)(a_row * (APAD * 2) + (k0 + a_kof) * 2);
            unsigned ah[4], al[4];
            ldsm_x4(ah[0], ah[1], ah[2], ah[3], ahb + a_off);
            ldsm_x4(al[0], al[1], al[2], al[3], alb + a_off);
            #pragma unroll
            for (int g = 0; g < 2; g++) {
                int n0 = wn * 32 + g * 16;
                unsigned b_off = (unsigned)((k0 + b_k) * (BPAD * 2) + (n0 + b_n) * 2);
                unsigned h0, h1, h2, h3, q0, q1, q2, q3;
                ldsm_x4_t(h0, h1, h2, h3, bhb + b_off);
                ldsm_x4_t(q0, q1, q2, q3, blb + b_off);
                mma_bf16(c[2 * g],     ah, h0, h1);
                mma_bf16(c[2 * g + 1], ah, h2, h3);
                mma_bf16(c[2 * g],     ah, q0, q1);
                mma_bf16(c[2 * g + 1], ah, q2, q3);
                mma_bf16(c[2 * g],     al, h0, h1);
                mma_bf16(c[2 * g + 1], al, h2, h3);
            }
        }
        if (kt < 95) {
            *(uint4*)&Ah[nxt][a_r0 * APAD + a_k8] = pah;
            *(uint4*)&Al[nxt][a_r0 * APAD + a_k8] = pal;
            *(uint4*)&Bh[nxt][b_kk * BPAD + b_n8] = pbh;
            *(uint4*)&Bl[nxt][b_kk * BPAD + b_n8] = pbl;
        }
        __syncthreads();
    }
    int r0 = rowBase + wm * 16 + (l >> 2);
    #pragma unroll
    for (int nb = 0; nb < 4; nb++) {
        int col = wn * 32 + nb * 8 + (l & 3) * 2;
        float2 bp = *(const float2*)&g_bp[col];
        float2 v0, v1;
        v0.x = fmaxf(c[nb][0] + bp.x, 0.f);
        v0.y = fmaxf(c[nb][1] + bp.y, 0.f);
        v1.x = fmaxf(c[nb][2] + bp.x, 0.f);
        v1.y = fmaxf(c[nb][3] + bp.y, 0.f);
        if (col < 32) {
            *(float2*)&g_in0[r0 * D + col] = v0;
            *(float2*)&g_in0[(r0 + 8) * D + col] = v1;
        } else {
            *(float2*)&g_in1[r0 * D + col - 32] = v0;
            *(float2*)&g_in1[(r0 + 8) * D + col - 32] = v1;
        }
    }
}

// ---------------- chain (R14, unchanged) ----------------
#define EDGE_ACC(E, SLOT)                                                     \
    do {                                                                      \
        const float* wp = Wd + (E) * 1024 + j0;                               \
        const float* wgp = Wg + (E) * 32;                                     \
        float4 b4 = __ldg((const float4*)&bd[(E) * 32 + j0]);                 \
        float d00 = b4.x, d01 = b4.y, d02 = b4.z, d03 = b4.w;                 \
        float d10 = b4.x, d11 = b4.y, d12 = b4.z, d13 = b4.w;                 \
        float g0 = 0.f, g1 = 0.f;                                             \
        _Pragma("unroll")                                                     \
        for (int k = 0; k < 32; k++) {                                        \
            float2 a2 = *(const float2*)&actT[(SLOT)][k][r0];                 \
            float4 w4 = __ldg((const float4*)&wp[k * 32]);                    \
            float wgk = __ldg(&wgp[k]);                                       \
            d00 += a2.x * w4.x; d01 += a2.x * w4.y;                           \
            d02 += a2.x * w4.z; d03 += a2.x * w4.w;                           \
            d10 += a2.y * w4.x; d11 += a2.y * w4.y;                           \
            d12 += a2.y * w4.z; d13 += a2.y * w4.w;                           \
            g0 += a2.x * wgk; g1 += a2.y * wgk;                               \
        }                                                                     \
        g0 = fminf(fmaxf(g0, 0.f), 1.f);                                      \
        g1 = fminf(fmaxf(g1, 0.f), 1.f);                                      \
        if (cg == 0) { stg[r0] += g0; stg[r0 + 1] += g1; }                    \
        n00 += g0 * d00; n01 += g0 * d01; n02 += g0 * d02; n03 += g0 * d03;   \
        n10 += g1 * d10; n11 += g1 * d11; n12 += g1 * d12; n13 += g1 * d13;   \
    } while (0)

__global__ void __launch_bounds__(256, 1) chain_kernel(
    const float* __restrict__ Wg, const float* __restrict__ Wd,
    const float* __restrict__ bd, float* __restrict__ tg) {
    __shared__ __align__(16) float actT[4][32][68];
    __shared__ float stg[64];
    __shared__ float smean[32], srstd[32];
    __shared__ float red1[8][32], red2[8][32];

    int tid = threadIdx.x;
    int blk = blockIdx.x;
    int rowBase = blk * 64;
    int rg = tid >> 3, r0 = rg * 2;
    int cg = tid & 7, j0 = cg * 4;
    int warp = tid >> 5, lane = tid & 31;
    int nd = tid >> 3, nrg = (tid & 7) * 8;
    if (tid < 64) stg[tid] = 0.f;

    float acc00, acc01, acc02, acc03, acc10, acc11, acc12, acc13;
    {
        float4 v0 = *(const float4*)&g_in0[(rowBase + r0) * D + j0];
        float4 v1 = *(const float4*)&g_in0[(rowBase + r0 + 1) * D + j0];
        acc00 = v0.x; acc01 = v0.y; acc02 = v0.z; acc03 = v0.w;
        acc10 = v1.x; acc11 = v1.y; acc12 = v1.z; acc13 = v1.w;
    }
    __syncthreads();

    for (int t = 0; t < 16; t++) {
        int slot_t = t & 3;
        float v00 = fmaxf(acc00, 0.f), v01 = fmaxf(acc01, 0.f);
        float v02 = fmaxf(acc02, 0.f), v03 = fmaxf(acc03, 0.f);
        float v10 = fmaxf(acc10, 0.f), v11 = fmaxf(acc11, 0.f);
        float v12 = fmaxf(acc12, 0.f), v13 = fmaxf(acc13, 0.f);
        *(float2*)&actT[slot_t][j0][r0]     = make_float2(v00, v10);
        *(float2*)&actT[slot_t][j0 + 1][r0] = make_float2(v01, v11);
        *(float2*)&actT[slot_t][j0 + 2][r0] = make_float2(v02, v12);
        *(float2*)&actT[slot_t][j0 + 3][r0] = make_float2(v03, v13);
        float s1c[4], s2c[4];
        s1c[0] = v00 + v10; s2c[0] = v00 * v00 + v10 * v10;
        s1c[1] = v01 + v11; s2c[1] = v01 * v01 + v11 * v11;
        s1c[2] = v02 + v12; s2c[2] = v02 * v02 + v12 * v12;
        s1c[3] = v03 + v13; s2c[3] = v03 * v03 + v13 * v13;
        #pragma unroll
        for (int c = 0; c < 4; c++) {
            s1c[c] += __shfl_xor_sync(~0u, s1c[c], 8);
            s2c[c] += __shfl_xor_sync(~0u, s2c[c], 8);
            s1c[c] += __shfl_xor_sync(~0u, s1c[c], 16);
            s2c[c] += __shfl_xor_sync(~0u, s2c[c], 16);
        }
        if (lane < 8) {
            *(float4*)&red1[warp][lane * 4] = make_float4(s1c[0], s1c[1], s1c[2], s1c[3]);
            *(float4*)&red2[warp][lane * 4] = make_float4(s2c[0], s2c[1], s2c[2], s2c[3]);
        }
        __syncthreads();
        if (warp == 0) {
            float s1 = 0.f, s2 = 0.f;
            #pragma unroll
            for (int g = 0; g < 8; g++) { s1 += red1[g][lane]; s2 += red2[g][lane]; }
            g_p1s[(t * CB + blk) * 32 + lane] = s1;
            g_p2s[(t * CB + blk) * 32 + lane] = s2;
        }
        __syncthreads();
        if (tid == 0) {
            __threadfence();
            *(volatile unsigned*)&g_cflag[blk] = (unsigned)(t + 1);
        }
        int tt = t + 1;
        float n00 = 0.f, n01 = 0.f, n02 = 0.f, n03 = 0.f;
        float n10 = 0.f, n11 = 0.f, n12 = 0.f, n13 = 0.f;
        int tec = 0, teb = 0, ts0 = 0;
        if (tt < 16) {
            if (tt == 1) {
                float4 v0 = *(const float4*)&g_in1[(rowBase + r0) * D + j0];
                float4 v1 = *(const float4*)&g_in1[(rowBase + r0 + 1) * D + j0];
                n00 = v0.x; n01 = v0.y; n02 = v0.z; n03 = v0.w;
                n10 = v1.x; n11 = v1.y; n12 = v1.z; n13 = v1.w;
            }
            tec = (tt < 4) ? tt : 4;
            ts0 = (tt - 4 < 0) ? 0 : tt - 4;
            teb = (tt <= 1) ? 0 : (tt == 2) ? 1 : (tt == 3) ? 3 : (tt == 4) ? 6
                                : 10 + (tt - 5) * 4;
            for (int ei = 0; ei < tec - 1; ei++) {
                int e = teb + ei, slot = (ts0 + ei) & 3;
                EDGE_ACC(e, slot);
            }
        }
        if (warp == 0) {
            unsigned need = (unsigned)(t + 1);
            volatile unsigned* vf = g_cflag;
            bool ok;
            do {
                unsigned f0 = vf[lane];
                unsigned f1 = vf[lane + 32];
                unsigned f2 = vf[lane + 64];
                unsigned f3 = vf[lane + 96];
                unsigned mn = min(min(f0, f1), min(f2, f3));
                ok = __all_sync(~0u, mn >= need);
            } while (!ok);
            __threadfence();
        }
        __syncthreads();
        {
            float s1 = 0.f, s2 = 0.f;
            #pragma unroll
            for (int q = 0; q < 16; q++) {
                int b = warp + q * 8;
                s1 += __ldcg(&g_p1s[(t * CB + b) * 32 + lane]);
                s2 += __ldcg(&g_p2s[(t * CB + b) * 32 + lane]);
            }
            red1[warp][lane] = s1;
            red2[warp][lane] = s2;
        }
        __syncthreads();
        if (warp == 0) {
            float s1 = 0.f, s2 = 0.f;
            #pragma unroll
            for (int g = 0; g < 8; g++) { s1 += red1[g][lane]; s2 += red2[g][lane]; }
            float mean = s1 * (1.f / BATCH);
            float var = s2 * (1.f / BATCH) - mean * mean;
            smean[lane] = mean;
            srstd[lane] = rsqrtf(var + BN_EPS);
        }
        __syncthreads();
        {
            float m = smean[nd], r = srstd[nd];
            #pragma unroll
            for (int q2 = 0; q2 < 2; q2++) {
                float4 vv = *(float4*)&actT[slot_t][nd][nrg + q2 * 4];
                vv.x = (vv.x - m) * r; vv.y = (vv.y - m) * r;
                vv.z = (vv.z - m) * r; vv.w = (vv.w - m) * r;
                *(float4*)&actT[slot_t][nd][nrg + q2 * 4] = vv;
                if (t >= 14) {
                    int krow = (t - 14) * 32 + nd;
                    uint2 hv, lv;
                    hv.x = pack_hi2(vv.x, vv.y); hv.y = pack_hi2(vv.z, vv.w);
                    lv.x = pack_lo2(vv.x, vv.y); lv.y = pack_lo2(vv.z, vv.w);
                    *(uint2*)&g_preTH[krow * BATCH + rowBase + nrg + q2 * 4] = hv;
                    *(uint2*)&g_preTL[krow * BATCH + rowBase + nrg + q2 * 4] = lv;
                }
            }
        }
        __syncthreads();
        if (tt < 16) {
            int e = teb + tec - 1;
            EDGE_ACC(e, slot_t);
        }
        acc00 = n00; acc01 = n01; acc02 = n02; acc03 = n03;
        acc10 = n10; acc11 = n11; acc12 = n12; acc13 = n13;
    }
    __syncthreads();
    if (tid < 64) tg[rowBase + tid] = stg[tid];
}

// ---------------- output GEMM (R14, unchanged) ----------------
#define ATM 72
#define AST 72
__global__ void __launch_bounds__(256) gemm_out_tc(float* __restrict__ out) {
    __shared__ __nv_bfloat16 ATh[64 * ATM];
    __shared__ __nv_bfloat16 ATl[64 * ATM];
    __shared__ __nv_bfloat16 Bh[64 * AST];
    __shared__ __nv_bfloat16 Bl[64 * AST];
    int tid = threadIdx.x;
    int w = tid >> 5, l = tid & 31;
    int wm = w & 3, wn = w >> 2;
    int rowBase = blockIdx.x * 64;
    int colBase = blockIdx.y * 64;
    unsigned ah_b = smem_u32(ATh), al_b = smem_u32(ATl);
    unsigned bh_b = smem_u32(Bh), bl_b = smem_u32(Bl);

    #pragma unroll
    for (int p = 0; p < 2; p++) {
        int idx = p * 256 + tid;
        int k = idx >> 3;
        int m8 = (idx & 7) * 8;
        *(uint4*)&ATh[k * ATM + m8] = *(const uint4*)&g_preTH[k * BATCH + rowBase + m8];
        *(uint4*)&ATl[k * ATM + m8] = *(const uint4*)&g_preTL[k * BATCH + rowBase + m8];
    }
    #pragma unroll
    for (int p = 0; p < 2; p++) {
        int idx = p * 256 + tid;
        int k = idx >> 3;
        int n8 = (idx & 7) * 8;
        *(uint4*)&Bh[k * AST + n8] = *(const uint4*)&g_WoutH[k * 1024 + colBase + n8];
        *(uint4*)&Bl[k * AST + n8] = *(const uint4*)&g_WoutL[k * 1024 + colBase + n8];
    }
    __syncthreads();

    float c[4][4];
    #pragma unroll
    for (int i = 0; i < 4; i++)
        #pragma unroll
        for (int j = 0; j < 4; j++) c[i][j] = 0.f;

    int a_k = (l & 7) + (l >> 4) * 8;
    int a_m = wm * 16 + ((l >> 3) & 1) * 8;
    int b_k = (l & 7) + ((l >> 3) & 1) * 8;
    int b_n = (l >> 4) * 8;

    #pragma unroll
    for (int ks = 0; ks < 4; ks++) {
        int k0 = ks * 16;
        unsigned a_off = (unsigned)((k0 + a_k) * (ATM * 2) + a_m * 2);
        unsigned ah[4], al[4];
        ldsm_x4_t(ah[0], ah[1], ah[2], ah[3], ah_b + a_off);
        ldsm_x4_t(al[0], al[1], al[2], al[3], al_b + a_off);
        #pragma unroll
        for (int g = 0; g < 2; g++) {
            int n0 = wn * 32 + g * 16;
            unsigned b_off = (unsigned)((k0 + b_k) * (AST * 2) + (n0 + b_n) * 2);
            unsigned h0, h1, h2, h3, q0, q1, q2, q3;
            ldsm_x4_t(h0, h1, h2, h3, bh_b + b_off);
            ldsm_x4_t(q0, q1, q2, q3, bl_b + b_off);
            mma_bf16(c[2 * g],     ah, h0, h1);
            mma_bf16(c[2 * g + 1], ah, h2, h3);
            mma_bf16(c[2 * g],     ah, q0, q1);
            mma_bf16(c[2 * g + 1], ah, q2, q3);
            mma_bf16(c[2 * g],     al, h0, h1);
            mma_bf16(c[2 * g + 1], al, h2, h3);
        }
    }
    int r0 = rowBase + wm * 16 + (l >> 2);
    #pragma unroll
    for (int nb = 0; nb < 4; nb++) {
        int col = colBase + wn * 32 + nb * 8 + (l & 3) * 2;
        if (col < NOUT) {
            float2 v0 = make_float2(c[nb][0], c[nb][1]);
            float2 v1 = make_float2(c[nb][2], c[nb][3]);
            *(float2*)&out[(size_t)r0 * NOUT + col] = v0;
            *(float2*)&out[(size_t)(r0 + 8) * NOUT + col] = v1;
        }
    }
}

// ---------------- launch ----------------
extern "C" void kernel_launch(void* const* d_in, const int* in_sizes, int n_in,
                              void* d_out, int out_size) {
    const float* x     = (const float*)d_in[0];
    const float* gamma = (const float*)d_in[1];
    const float* beta  = (const float*)d_in[2];
    const float* W_in  = (const float*)d_in[3];
    const float* b_in  = (const float*)d_in[4];
    const float* Wg    = (const float*)d_in[5];
    const float* Wd    = (const float*)d_in[6];
    const float* bd    = (const float*)d_in[7];
    const float* Wout  = (const float*)d_in[8];
    float* out = (float*)d_out;

    float* tg;
    if (out_size >= BATCH * NOUT + BATCH) {
        tg = out + (size_t)BATCH * NOUT;
    } else {
        void* p = nullptr;
        cudaGetSymbolAddress(&p, g_tg_fallback);
        tg = (float*)p;
    }

    prep_kernel<<<PB, 256>>>(x, gamma, beta, W_in, b_in);
    woutfold_kernel<<<4, 256>>>(Wout);
    gemm_in_tc<<<128, 256>>>(x);
    chain_kernel<<<CB, 256>>>(Wg, Wd, bd, tg);
    gemm_out_tc<<<dim3(128, 16), 256>>>(out);
}

// round 17
// speedup vs baseline: 1.2031x; 1.2031x over previous
#include <cuda_runtime.h>
#include <cuda_bf16.h>
#include <stdint.h>
#include <math.h>

#define NBANKS 16
#define D 32
#define NIN 3072
#define NOUT 1000
#define BATCH 8192
#define BN_EPS 1e-5f
#define CB 128
#define PB 128

// ---------------- device scratch ----------------
__device__ float g_px1[PB * NIN];
__device__ float g_px2[PB * NIN];
__device__ float g_scale[NIN];
__device__ float g_shift[NIN];
__device__ float g_bpart[PB * 64];
__device__ __nv_bfloat16 g_WpH[NIN * 64];
__device__ __nv_bfloat16 g_WpL[NIN * 64];
__device__ float g_bp[64];
__device__ float g_in0[BATCH * D];
__device__ float g_in1[BATCH * D];
__device__ __nv_bfloat16 g_preTH[64 * BATCH];
__device__ __nv_bfloat16 g_preTL[64 * BATCH];
__device__ __nv_bfloat16 g_WoutH[64 * 1024];
__device__ __nv_bfloat16 g_WoutL[64 * 1024];
__device__ float g_p1s[NBANKS * CB * 32];
__device__ float g_p2s[NBANKS * CB * 32];
__device__ unsigned g_barc;
__device__ unsigned g_barg;
__device__ unsigned g_belect;
__device__ unsigned g_cflag[CB];
__device__ float g_tg_fallback[BATCH];

// chain dynamic smem layout (bytes)
#define SM_ACT   0            // float[4][32][68]  = 34816
#define SM_WD    34816        // float[4][1024]    = 16384
#define SM_WG    51200        // float[4][32]      = 512
#define SM_BD    51712        // float[4][32]      = 512
#define SM_STG   52224        // float[64]         = 256
#define SM_MEAN  52480        // float[32]         = 128
#define SM_RSTD  52608        // float[32]         = 128
#define SM_RED1  52736        // float[8][32]      = 1024
#define SM_RED2  53760        // float[8][32]      = 1024
#define SM_TOTAL 54784

// ---------------- helpers ----------------
__device__ __forceinline__ unsigned smem_u32(const void* p) {
    return (unsigned)__cvta_generic_to_shared(p);
}
__device__ __forceinline__ void ldsm_x4(unsigned& r0, unsigned& r1, unsigned& r2,
                                        unsigned& r3, unsigned addr) {
    asm volatile("ldmatrix.sync.aligned.m8n8.x4.shared.b16 {%0,%1,%2,%3},[%4];"
                 : "=r"(r0), "=r"(r1), "=r"(r2), "=r"(r3) : "r"(addr));
}
__device__ __forceinline__ void ldsm_x4_t(unsigned& r0, unsigned& r1, unsigned& r2,
                                          unsigned& r3, unsigned addr) {
    asm volatile("ldmatrix.sync.aligned.m8n8.x4.trans.shared.b16 {%0,%1,%2,%3},[%4];"
                 : "=r"(r0), "=r"(r1), "=r"(r2), "=r"(r3) : "r"(addr));
}
__device__ __forceinline__ void mma_bf16(float* c, const unsigned* a,
                                         unsigned b0, unsigned b1) {
    asm volatile(
        "mma.sync.aligned.m16n8k16.row.col.f32.bf16.bf16.f32 "
        "{%0,%1,%2,%3},{%4,%5,%6,%7},{%8,%9},{%0,%1,%2,%3};"
        : "+f"(c[0]), "+f"(c[1]), "+f"(c[2]), "+f"(c[3])
        : "r"(a[0]), "r"(a[1]), "r"(a[2]), "r"(a[3]), "r"(b0), "r"(b1));
}
__device__ __forceinline__ unsigned pack_hi2(float x, float y) {
    __nv_bfloat16 hx = __float2bfloat16(x), hy = __float2bfloat16(y);
    return ((unsigned)__bfloat16_as_ushort(hy) << 16) | __bfloat16_as_ushort(hx);
}
__device__ __forceinline__ unsigned pack_lo2(float x, float y) {
    __nv_bfloat16 hx = __float2bfloat16(x), hy = __float2bfloat16(y);
    float lx = x - __bfloat162float(hx), ly = y - __bfloat162float(hy);
    __nv_bfloat16 bx = __float2bfloat16(lx), by = __float2bfloat16(ly);
    return ((unsigned)__bfloat16_as_ushort(by) << 16) | __bfloat16_as_ushort(bx);
}

__device__ __forceinline__ void grid_bar_n(int nblk) {
    __syncthreads();
    if (threadIdx.x == 0) {
        unsigned gen = *(volatile unsigned*)&g_barg;
        __threadfence();
        if (atomicAdd(&g_barc, 1u) == (unsigned)nblk - 1) {
            atomicExch(&g_barc, 0u);
            __threadfence();
            *(volatile unsigned*)&g_barg = gen + 1;
        } else {
            while (*(volatile unsigned*)&g_barg == gen) { }
        }
        __threadfence();
    }
    __syncthreads();
}

// ---------------- fused prep (R14) ----------------
__global__ void __launch_bounds__(256, 1) prep_kernel(
    const float* __restrict__ x, const float* __restrict__ gamma,
    const float* __restrict__ beta, const float* __restrict__ W_in,
    const float* __restrict__ b_in) {
    int tid = threadIdx.x;
    int blk = blockIdx.x;
    int warp = tid >> 5, lane = tid & 31;

    if (blk == 0) {
        if (tid < CB) g_cflag[tid] = 0u;
        if (tid == 0) g_belect = 0u;
    }

    {
        float s1[3][4], s2[3][4];
        #pragma unroll
        for (int g = 0; g < 3; g++)
            #pragma unroll
            for (int i = 0; i < 4; i++) { s1[g][i] = 0.f; s2[g][i] = 0.f; }
        int row0 = blk * 64;
        for (int r = 0; r < 64; r++) {
            const float* xr = x + (size_t)(row0 + r) * NIN;
            #pragma unroll
            for (int g = 0; g < 3; g++) {
                float4 v = *(const float4*)&xr[g * 1024 + tid * 4];
                s1[g][0] += v.x; s2[g][0] += v.x * v.x;
                s1[g][1] += v.y; s2[g][1] += v.y * v.y;
                s1[g][2] += v.z; s2[g][2] += v.z * v.z;
                s1[g][3] += v.w; s2[g][3] += v.w * v.w;
            }
        }
        #pragma unroll
        for (int g = 0; g < 3; g++) {
            *(float4*)&g_px1[blk * NIN + g * 1024 + tid * 4] =
                make_float4(s1[g][0], s1[g][1], s1[g][2], s1[g][3]);
            *(float4*)&g_px2[blk * NIN + g * 1024 + tid * 4] =
                make_float4(s2[g][0], s2[g][1], s2[g][2], s2[g][3]);
        }
    }
    grid_bar_n(PB);
    {
        #pragma unroll
        for (int cc = 0; cc < 3; cc++) {
            int col = blk * 24 + warp * 3 + cc;
            float a = 0.f, b = 0.f;
            #pragma unroll
            for (int q = 0; q < 4; q++) {
                a += g_px1[(lane + q * 32) * NIN + col];
                b += g_px2[(lane + q * 32) * NIN + col];
            }
            #pragma unroll
            for (int o = 16; o; o >>= 1) {
                a += __shfl_xor_sync(~0u, a, o);
                b += __shfl_xor_sync(~0u, b, o);
            }
            if (lane == 0) {
                float mean = a * (1.f / BATCH);
                float var = b * (1.f / BATCH) - mean * mean;
                float rstd = rsqrtf(var + BN_EPS);
                float sc = rstd * gamma[col];
                g_scale[col] = sc;
                g_shift[col] = beta[col] - mean * sc;
            }
        }
    }
    __syncthreads();
    {
        __shared__ float sred[4][64];
        int j = tid & 63, grp = tid >> 6;
        int k = j >> 5, d = j & 31;
        float bias = 0.f;
        #pragma unroll
        for (int p = 0; p < 6; p++) {
            int c = blk * 24 + grp * 6 + p;
            float wraw = W_in[(size_t)k * NIN * D + c * D + d];
            float w = g_scale[c] * wraw;
            __nv_bfloat16 h = __float2bfloat16(w);
            g_WpH[c * 64 + j] = h;
            g_WpL[c * 64 + j] = __float2bfloat16(w - __bfloat162float(h));
            bias += g_shift[c] * wraw;
        }
        sred[grp][j] = bias;
        __syncthreads();
        if (tid < 64)
            g_bpart[blk * 64 + tid] =
                sred[0][tid] + sred[1][tid] + sred[2][tid] + sred[3][tid];
    }
    __syncthreads();
    __shared__ unsigned s_elect;
    if (tid == 0) {
        __threadfence();
        s_elect = (atomicAdd(&g_belect, 1u) == PB - 1) ? 1u : 0u;
    }
    __syncthreads();
    if (s_elect) {
        if (tid == 0) { atomicExch(&g_belect, 0u); __threadfence(); }
        __shared__ float sred2[4][64];
        int j = tid & 63, grp = tid >> 6;
        float s = 0.f;
        #pragma unroll 8
        for (int b = grp; b < PB; b += 4) s += __ldcg(&g_bpart[b * 64 + j]);
        sred2[grp][j] = s;
        __syncthreads();
        if (tid < 64)
            g_bp[tid] = b_in[tid] +
                sred2[0][tid] + sred2[1][tid] + sred2[2][tid] + sred2[3][tid];
    }
}

__global__ void woutfold_kernel(const float* __restrict__ Wout) {
    int n = blockIdx.x * 256 + threadIdx.x;
    #pragma unroll 8
    for (int k = 0; k < 64; k++) {
        int bank = k >> 5, d = k & 31;
        float w = (n < NOUT) ? Wout[(size_t)bank * D * NOUT + d * NOUT + n] : 0.f;
        __nv_bfloat16 h = __float2bfloat16(w);
        g_WoutH[k * 1024 + n] = h;
        g_WoutL[k * 1024 + n] = __float2bfloat16(w - __bfloat162float(h));
    }
}

// ---------------- input GEMM (R14, unchanged) ----------------
#define APAD 40
#define BPAD 72
__global__ void __launch_bounds__(256) gemm_in_tc(const float* __restrict__ x) {
    __shared__ __nv_bfloat16 Ah[2][64 * APAD];
    __shared__ __nv_bfloat16 Al[2][64 * APAD];
    __shared__ __nv_bfloat16 Bh[2][32 * BPAD];
    __shared__ __nv_bfloat16 Bl[2][32 * BPAD];
    int tid = threadIdx.x;
    int w = tid >> 5, l = tid & 31;
    int wm = w & 3, wn = w >> 2;
    int rowBase = blockIdx.x * 64;

    int a_r0 = tid >> 3;
    int a_k4 = (tid & 7) * 4;
    int b_kk = tid >> 3;
    int b_n8 = (tid & 7) * 8;

    float4 pa0, pa1;
    uint4 pbh, pbl;
    pa0 = *(const float4*)&x[(size_t)(rowBase + a_r0) * NIN + a_k4];
    pa1 = *(const float4*)&x[(size_t)(rowBase + a_r0 + 32) * NIN + a_k4];
    pbh = *(const uint4*)&g_WpH[b_kk * 64 + b_n8];
    pbl = *(const uint4*)&g_WpL[b_kk * 64 + b_n8];
    {
        uint2 h0, l0;
        h0.x = pack_hi2(pa0.x, pa0.y); h0.y = pack_hi2(pa0.z, pa0.w);
        l0.x = pack_lo2(pa0.x, pa0.y); l0.y = pack_lo2(pa0.z, pa0.w);
        *(uint2*)&Ah[0][a_r0 * APAD + a_k4] = h0;
        *(uint2*)&Al[0][a_r0 * APAD + a_k4] = l0;
        h0.x = pack_hi2(pa1.x, pa1.y); h0.y = pack_hi2(pa1.z, pa1.w);
        l0.x = pack_lo2(pa1.x, pa1.y); l0.y = pack_lo2(pa1.z, pa1.w);
        *(uint2*)&Ah[0][(a_r0 + 32) * APAD + a_k4] = h0;
        *(uint2*)&Al[0][(a_r0 + 32) * APAD + a_k4] = l0;
        *(uint4*)&Bh[0][b_kk * BPAD + b_n8] = pbh;
        *(uint4*)&Bl[0][b_kk * BPAD + b_n8] = pbl;
    }
    __syncthreads();

    float c[4][4];
    #pragma unroll
    for (int i = 0; i < 4; i++)
        #pragma unroll
        for (int j = 0; j < 4; j++) c[i][j] = 0.f;

    int a_row = wm * 16 + (l & 7) + ((l >> 3) & 1) * 8;
    int a_kof = (l >> 4) * 8;
    int b_k = (l & 7) + ((l >> 3) & 1) * 8;
    int b_n = (l >> 4) * 8;

    for (int kt = 0; kt < 96; kt++) {
        int cur = kt & 1, nxt = cur ^ 1;
        if (kt < 95) {
            int kb = (kt + 1) * 32;
            pa0 = *(const float4*)&x[(size_t)(rowBase + a_r0) * NIN + kb + a_k4];
            pa1 = *(const float4*)&x[(size_t)(rowBase + a_r0 + 32) * NIN + kb + a_k4];
            pbh = *(const uint4*)&g_WpH[(kb + b_kk) * 64 + b_n8];
            pbl = *(const uint4*)&g_WpL[(kb + b_kk) * 64 + b_n8];
        }
        unsigned ahb = smem_u32(Ah[cur]), alb = smem_u32(Al[cur]);
        unsigned bhb = smem_u32(Bh[cur]), blb = smem_u32(Bl[cur]);
        #pragma unroll
        for (int ks = 0; ks < 2; ks++) {
            int k0 = ks * 16;
            unsigned a_off = (unsigned)(a_row * (APAD * 2) + (k0 + a_kof) * 2);
            unsigned ah[4], al[4];
            ldsm_x4(ah[0], ah[1], ah[2], ah[3], ahb + a_off);
            ldsm_x4(al[0], al[1], al[2], al[3], alb + a_off);
            #pragma unroll
            for (int g = 0; g < 2; g++) {
                int n0 = wn * 32 + g * 16;
                unsigned b_off = (unsigned)((k0 + b_k) * (BPAD * 2) + (n0 + b_n) * 2);
                unsigned h0, h1, h2, h3, q0, q1, q2, q3;
                ldsm_x4_t(h0, h1, h2, h3, bhb + b_off);
                ldsm_x4_t(q0, q1, q2, q3, blb + b_off);
                mma_bf16(c[2 * g],     ah, h0, h1);
                mma_bf16(c[2 * g + 1], ah, h2, h3);
                mma_bf16(c[2 * g],     ah, q0, q1);
                mma_bf16(c[2 * g + 1], ah, q2, q3);
                mma_bf16(c[2 * g],     al, h0, h1);
                mma_bf16(c[2 * g + 1], al, h2, h3);
            }
        }
        if (kt < 95) {
            uint2 h0, l0;
            h0.x = pack_hi2(pa0.x, pa0.y); h0.y = pack_hi2(pa0.z, pa0.w);
            l0.x = pack_lo2(pa0.x, pa0.y); l0.y = pack_lo2(pa0.z, pa0.w);
            *(uint2*)&Ah[nxt][a_r0 * APAD + a_k4] = h0;
            *(uint2*)&Al[nxt][a_r0 * APAD + a_k4] = l0;
            h0.x = pack_hi2(pa1.x, pa1.y); h0.y = pack_hi2(pa1.z, pa1.w);
            l0.x = pack_lo2(pa1.x, pa1.y); l0.y = pack_lo2(pa1.z, pa1.w);
            *(uint2*)&Ah[nxt][(a_r0 + 32) * APAD + a_k4] = h0;
            *(uint2*)&Al[nxt][(a_r0 + 32) * APAD + a_k4] = l0;
            *(uint4*)&Bh[nxt][b_kk * BPAD + b_n8] = pbh;
            *(uint4*)&Bl[nxt][b_kk * BPAD + b_n8] = pbl;
        }
        __syncthreads();
    }
    int r0 = rowBase + wm * 16 + (l >> 2);
    #pragma unroll
    for (int nb = 0; nb < 4; nb++) {
        int col = wn * 32 + nb * 8 + (l & 3) * 2;
        float2 bp = *(const float2*)&g_bp[col];
        float2 v0, v1;
        v0.x = fmaxf(c[nb][0] + bp.x, 0.f);
        v0.y = fmaxf(c[nb][1] + bp.y, 0.f);
        v1.x = fmaxf(c[nb][2] + bp.x, 0.f);
        v1.y = fmaxf(c[nb][3] + bp.y, 0.f);
        if (col < 32) {
            *(float2*)&g_in0[r0 * D + col] = v0;
            *(float2*)&g_in0[(r0 + 8) * D + col] = v1;
        } else {
            *(float2*)&g_in1[r0 * D + col - 32] = v0;
            *(float2*)&g_in1[(r0 + 8) * D + col - 32] = v1;
        }
    }
}

// ---------------- chain: dynamic smem, weights staged per bank -------------
// Per thread: 2 rows x 4 cols. EDGE_ACC reads only shared memory.
#define EDGE_ACC(EI, SLOT)                                                    \
    do {                                                                      \
        float4 b4 = *(const float4*)&sbd2[(EI) * 32 + j0];                    \
        float d00 = b4.x, d01 = b4.y, d02 = b4.z, d03 = b4.w;                 \
        float d10 = b4.x, d11 = b4.y, d12 = b4.z, d13 = b4.w;                 \
        float g0 = 0.f, g1 = 0.f;                                             \
        _Pragma("unroll")                                                     \
        for (int k = 0; k < 32; k++) {                                        \
            float2 a2 = *(const float2*)&actT[(SLOT)][k][r0];                 \
            float4 w4 = *(const float4*)&sWd[(EI) * 1024 + k * 32 + j0];      \
            float wgk = sWgv[(EI) * 32 + k];                                  \
            d00 += a2.x * w4.x; d01 += a2.x * w4.y;                           \
            d02 += a2.x * w4.z; d03 += a2.x * w4.w;                           \
            d10 += a2.y * w4.x; d11 += a2.y * w4.y;                           \
            d12 += a2.y * w4.z; d13 += a2.y * w4.w;                           \
            g0 += a2.x * wgk; g1 += a2.y * wgk;                               \
        }                                                                     \
        g0 = fminf(fmaxf(g0, 0.f), 1.f);                                      \
        g1 = fminf(fmaxf(g1, 0.f), 1.f);                                      \
        if (cg == 0) { stg[r0] += g0; stg[r0 + 1] += g1; }                    \
        n00 += g0 * d00; n01 += g0 * d01; n02 += g0 * d02; n03 += g0 * d03;   \
        n10 += g1 * d10; n11 += g1 * d11; n12 += g1 * d12; n13 += g1 * d13;   \
    } while (0)

__global__ void __launch_bounds__(256, 1) chain_kernel(
    const float* __restrict__ Wg, const float* __restrict__ Wd,
    const float* __restrict__ bd, float* __restrict__ tg) {
    extern __shared__ __align__(16) unsigned char smraw[];
    float (*actT)[32][68] = (float(*)[32][68])(smraw + SM_ACT);
    float* sWd   = (float*)(smraw + SM_WD);
    float* sWgv  = (float*)(smraw + SM_WG);
    float* sbd2  = (float*)(smraw + SM_BD);
    float* stg   = (float*)(smraw + SM_STG);
    float* smean = (float*)(smraw + SM_MEAN);
    float* srstd = (float*)(smraw + SM_RSTD);
    float (*red1)[32] = (float(*)[32])(smraw + SM_RED1);
    float (*red2)[32] = (float(*)[32])(smraw + SM_RED2);

    int tid = threadIdx.x;
    int blk = blockIdx.x;
    int rowBase = blk * 64;
    int rg = tid >> 3, r0 = rg * 2;
    int cg = tid & 7, j0 = cg * 4;
    int warp = tid >> 5, lane = tid & 31;
    int nd = tid >> 3, nrg = (tid & 7) * 8;
    if (tid < 64) stg[tid] = 0.f;

    float acc00, acc01, acc02, acc03, acc10, acc11, acc12, acc13;
    {
        float4 v0 = *(const float4*)&g_in0[(rowBase + r0) * D + j0];
        float4 v1 = *(const float4*)&g_in0[(rowBase + r0 + 1) * D + j0];
        acc00 = v0.x; acc01 = v0.y; acc02 = v0.z; acc03 = v0.w;
        acc10 = v1.x; acc11 = v1.y; acc12 = v1.z; acc13 = v1.w;
    }
    __syncthreads();

    for (int t = 0; t < 16; t++) {
        int slot_t = t & 3;
        float v00 = fmaxf(acc00, 0.f), v01 = fmaxf(acc01, 0.f);
        float v02 = fmaxf(acc02, 0.f), v03 = fmaxf(acc03, 0.f);
        float v10 = fmaxf(acc10, 0.f), v11 = fmaxf(acc11, 0.f);
        float v12 = fmaxf(acc12, 0.f), v13 = fmaxf(acc13, 0.f);
        *(float2*)&actT[slot_t][j0][r0]     = make_float2(v00, v10);
        *(float2*)&actT[slot_t][j0 + 1][r0] = make_float2(v01, v11);
        *(float2*)&actT[slot_t][j0 + 2][r0] = make_float2(v02, v12);
        *(float2*)&actT[slot_t][j0 + 3][r0] = make_float2(v03, v13);
        float s1c[4], s2c[4];
        s1c[0] = v00 + v10; s2c[0] = v00 * v00 + v10 * v10;
        s1c[1] = v01 + v11; s2c[1] = v01 * v01 + v11 * v11;
        s1c[2] = v02 + v12; s2c[2] = v02 * v02 + v12 * v12;
        s1c[3] = v03 + v13; s2c[3] = v03 * v03 + v13 * v13;
        #pragma unroll
        for (int c = 0; c < 4; c++) {
            s1c[c] += __shfl_xor_sync(~0u, s1c[c], 8);
            s2c[c] += __shfl_xor_sync(~0u, s2c[c], 8);
            s1c[c] += __shfl_xor_sync(~0u, s1c[c], 16);
            s2c[c] += __shfl_xor_sync(~0u, s2c[c], 16);
        }
        if (lane < 8) {
            *(float4*)&red1[warp][lane * 4] = make_float4(s1c[0], s1c[1], s1c[2], s1c[3]);
            *(float4*)&red2[warp][lane * 4] = make_float4(s2c[0], s2c[1], s2c[2], s2c[3]);
        }
        __syncthreads();
        int tt = t + 1;
        int tec = 0, teb = 0, ts0 = 0;
        if (tt < 16) {
            tec = (tt < 4) ? tt : 4;
            ts0 = (tt - 4 < 0) ? 0 : tt - 4;
            teb = (tt <= 1) ? 0 : (tt == 2) ? 1 : (tt == 3) ? 3 : (tt == 4) ? 6
                                : 10 + (tt - 5) * 4;
        }
        // publish partials (warp 0) + stage next-bank weights into smem
        if (warp == 0) {
            float s1 = 0.f, s2 = 0.f;
            #pragma unroll
            for (int g = 0; g < 8; g++) { s1 += red1[g][lane]; s2 += red2[g][lane]; }
            g_p1s[(t * CB + blk) * 32 + lane] = s1;
            g_p2s[(t * CB + blk) * 32 + lane] = s2;
        }
        if (tt < 16) {
            for (int p = tid; p < tec * 256; p += 256) {
                int ei = p >> 8, q = (p & 255) * 4;
                *(float4*)&sWd[ei * 1024 + q] =
                    __ldg((const float4*)&Wd[(teb + ei) * 1024 + q]);
            }
            if (tid < tec * 32) {
                int ei = tid >> 5, k = tid & 31;
                sWgv[ei * 32 + k] = __ldg(&Wg[(teb + ei) * 32 + k]);
                sbd2[ei * 32 + k] = __ldg(&bd[(teb + ei) * 32 + k]);
            }
        }
        __syncthreads();
        // barrier arrive
        if (tid == 0) {
            __threadfence();
            *(volatile unsigned*)&g_cflag[blk] = (unsigned)(t + 1);
        }
        // early edges for bank tt
        float n00 = 0.f, n01 = 0.f, n02 = 0.f, n03 = 0.f;
        float n10 = 0.f, n11 = 0.f, n12 = 0.f, n13 = 0.f;
        if (tt < 16) {
            if (tt == 1) {
                float4 v0 = *(const float4*)&g_in1[(rowBase + r0) * D + j0];
                float4 v1 = *(const float4*)&g_in1[(rowBase + r0 + 1) * D + j0];
                n00 = v0.x; n01 = v0.y; n02 = v0.z; n03 = v0.w;
                n10 = v1.x; n11 = v1.y; n12 = v1.z; n13 = v1.w;
            }
            for (int ei = 0; ei < tec - 1; ei++) {
                int slot = (ts0 + ei) & 3;
                EDGE_ACC(ei, slot);
            }
        }
        // barrier wait: warp 0 polls all flags (volatile)
        if (warp == 0) {
            unsigned need = (unsigned)(t + 1);
            volatile unsigned* vf = g_cflag;
            bool ok;
            do {
                unsigned f0 = vf[lane];
                unsigned f1 = vf[lane + 32];
                unsigned f2 = vf[lane + 64];
                unsigned f3 = vf[lane + 96];
                unsigned mn = min(min(f0, f1), min(f2, f3));
                ok = __all_sync(~0u, mn >= need);
            } while (!ok);
            __threadfence();
        }
        __syncthreads();
        // finalize stats for bank t
        {
            float s1 = 0.f, s2 = 0.f;
            #pragma unroll
            for (int q = 0; q < 16; q++) {
                int b = warp + q * 8;
                s1 += __ldcg(&g_p1s[(t * CB + b) * 32 + lane]);
                s2 += __ldcg(&g_p2s[(t * CB + b) * 32 + lane]);
            }
            red1[warp][lane] = s1;
            red2[warp][lane] = s2;
        }
        __syncthreads();
        if (warp == 0) {
            float s1 = 0.f, s2 = 0.f;
            #pragma unroll
            for (int g = 0; g < 8; g++) { s1 += red1[g][lane]; s2 += red2[g][lane]; }
            float mean = s1 * (1.f / BATCH);
            float var = s2 * (1.f / BATCH) - mean * mean;
            smean[lane] = mean;
            srstd[lane] = rsqrtf(var + BN_EPS);
        }
        __syncthreads();
        // normalize slot_t in place (+ export bf16 for banks 14/15)
        {
            float m = smean[nd], r = srstd[nd];
            #pragma unroll
            for (int q2 = 0; q2 < 2; q2++) {
                float4 vv = *(float4*)&actT[slot_t][nd][nrg + q2 * 4];
                vv.x = (vv.x - m) * r; vv.y = (vv.y - m) * r;
                vv.z = (vv.z - m) * r; vv.w = (vv.w - m) * r;
                *(float4*)&actT[slot_t][nd][nrg + q2 * 4] = vv;
                if (t >= 14) {
                    int krow = (t - 14) * 32 + nd;
                    uint2 hv, lv;
                    hv.x = pack_hi2(vv.x, vv.y); hv.y = pack_hi2(vv.z, vv.w);
                    lv.x = pack_lo2(vv.x, vv.y); lv.y = pack_lo2(vv.z, vv.w);
                    *(uint2*)&g_preTH[krow * BATCH + rowBase + nrg + q2 * 4] = hv;
                    *(uint2*)&g_preTL[krow * BATCH + rowBase + nrg + q2 * 4] = lv;
                }
            }
        }
        __syncthreads();
        // late edge (source t, just normalized)
        if (tt < 16) {
            EDGE_ACC(tec - 1, slot_t);
        }
        acc00 = n00; acc01 = n01; acc02 = n02; acc03 = n03;
        acc10 = n10; acc11 = n11; acc12 = n12; acc13 = n13;
    }
    __syncthreads();
    if (tid < 64) tg[rowBase + tid] = stg[tid];
}

// ---------------- output GEMM (R14, unchanged) ----------------
#define ATM 72
#define AST 72
__global__ void __launch_bounds__(256) gemm_out_tc(float* __restrict__ out) {
    __shared__ __nv_bfloat16 ATh[64 * ATM];
    __shared__ __nv_bfloat16 ATl[64 * ATM];
    __shared__ __nv_bfloat16 Bh[64 * AST];
    __shared__ __nv_bfloat16 Bl[64 * AST];
    int tid = threadIdx.x;
    int w = tid >> 5, l = tid & 31;
    int wm = w & 3, wn = w >> 2;
    int rowBase = blockIdx.x * 64;
    int colBase = blockIdx.y * 64;
    unsigned ah_b = smem_u32(ATh), al_b = smem_u32(ATl);
    unsigned bh_b = smem_u32(Bh), bl_b = smem_u32(Bl);

    #pragma unroll
    for (int p = 0; p < 2; p++) {
        int idx = p * 256 + tid;
        int k = idx >> 3;
        int m8 = (idx & 7) * 8;
        *(uint4*)&ATh[k * ATM + m8] = *(const uint4*)&g_preTH[k * BATCH + rowBase + m8];
        *(uint4*)&ATl[k * ATM + m8] = *(const uint4*)&g_preTL[k * BATCH + rowBase + m8];
    }
    #pragma unroll
    for (int p = 0; p < 2; p++) {
        int idx = p * 256 + tid;
        int k = idx >> 3;
        int n8 = (idx & 7) * 8;
        *(uint4*)&Bh[k * AST + n8] = *(const uint4*)&g_WoutH[k * 1024 + colBase + n8];
        *(uint4*)&Bl[k * AST + n8] = *(const uint4*)&g_WoutL[k * 1024 + colBase + n8];
    }
    __syncthreads();

    float c[4][4];
    #pragma unroll
    for (int i = 0; i < 4; i++)
        #pragma unroll
        for (int j = 0; j < 4; j++) c[i][j] = 0.f;

    int a_k = (l & 7) + (l >> 4) * 8;
    int a_m = wm * 16 + ((l >> 3) & 1) * 8;
    int b_k = (l & 7) + ((l >> 3) & 1) * 8;
    int b_n = (l >> 4) * 8;

    #pragma unroll
    for (int ks = 0; ks < 4; ks++) {
        int k0 = ks * 16;
        unsigned a_off = (unsigned)((k0 + a_k) * (ATM * 2) + a_m * 2);
        unsigned ah[4], al[4];
        ldsm_x4_t(ah[0], ah[1], ah[2], ah[3], ah_b + a_off);
        ldsm_x4_t(al[0], al[1], al[2], al[3], al_b + a_off);
        #pragma unroll
        for (int g = 0; g < 2; g++) {
            int n0 = wn * 32 + g * 16;
            unsigned b_off = (unsigned)((k0 + b_k) * (AST * 2) + (n0 + b_n) * 2);
            unsigned h0, h1, h2, h3, q0, q1, q2, q3;
            ldsm_x4_t(h0, h1, h2, h3, bh_b + b_off);
            ldsm_x4_t(q0, q1, q2, q3, bl_b + b_off);
            mma_bf16(c[2 * g],     ah, h0, h1);
            mma_bf16(c[2 * g + 1], ah, h2, h3);
            mma_bf16(c[2 * g],     ah, q0, q1);
            mma_bf16(c[2 * g + 1], ah, q2, q3);
            mma_bf16(c[2 * g],     al, h0, h1);
            mma_bf16(c[2 * g + 1], al, h2, h3);
        }
    }
    int r0 = rowBase + wm * 16 + (l >> 2);
    #pragma unroll
    for (int nb = 0; nb < 4; nb++) {
        int col = colBase + wn * 32 + nb * 8 + (l & 3) * 2;
        if (col < NOUT) {
            float2 v0 = make_float2(c[nb][0], c[nb][1]);
            float2 v1 = make_float2(c[nb][2], c[nb][3]);
            *(float2*)&out[(size_t)r0 * NOUT + col] = v0;
            *(float2*)&out[(size_t)(r0 + 8) * NOUT + col] = v1;
        }
    }
}

// ---------------- launch ----------------
extern "C" void kernel_launch(void* const* d_in, const int* in_sizes, int n_in,
                              void* d_out, int out_size) {
    const float* x     = (const float*)d_in[0];
    const float* gamma = (const float*)d_in[1];
    const float* beta  = (const float*)d_in[2];
    const float* W_in  = (const float*)d_in[3];
    const float* b_in  = (const float*)d_in[4];
    const float* Wg    = (const float*)d_in[5];
    const float* Wd    = (const float*)d_in[6];
    const float* bd    = (const float*)d_in[7];
    const float* Wout  = (const float*)d_in[8];
    float* out = (float*)d_out;

    float* tg;
    if (out_size >= BATCH * NOUT + BATCH) {
        tg = out + (size_t)BATCH * NOUT;
    } else {
        void* p = nullptr;
        cudaGetSymbolAddress(&p, g_tg_fallback);
        tg = (float*)p;
    }

    // idempotent, host-side, called every time (no static guards)
    cudaFuncSetAttribute(chain_kernel,
                         cudaFuncAttributeMaxDynamicSharedMemorySize, SM_TOTAL);

    prep_kernel<<<PB, 256>>>(x, gamma, beta, W_in, b_in);
    woutfold_kernel<<<4, 256>>>(Wout);
    gemm_in_tc<<<128, 256>>>(x);
    chain_kernel<<<CB, 256, SM_TOTAL>>>(Wg, Wd, bd, tg);
    gemm_out_tc<<<dim3(128, 16), 256>>>(out);
}